// round 7
// baseline (speedup 1.0000x reference)
#include <cuda_runtime.h>
#include <cuda_pipeline.h>

typedef unsigned long long ull;

#define NIN   784
#define DD    10
#define WW    4
#define NOUT  10
#define NL    3
#define TPB   256
#define ROWS_PB 64
#define NC    49            // 784/16 k-chunks
#define WROW  68            // padded+swizzled floats per k-row of Wt
#define STG16 272           // 16*WROW*4/16 : 16B units per stage

// __device__ scratch (no allocation)
__device__ float Wt_g[NIN * WROW];           // k-major Win, swizzled og slices
__device__ float dwp_g[NL * 16 * DD * 12];   // data_w, e padded 10->12

__global__ void prep_kernel(const float* __restrict__ Win,
                            const float* __restrict__ dw)
{
    int i = blockIdx.x * blockDim.x + threadIdx.x;
    if (i < NIN * WROW) {
        int k = i / WROW, c = i % WROW;
        float v = 0.0f;
        int og = -1, j = 0;
        if (c < 32)              { og = c >> 3;            j = c & 7; }
        else if (c >= 36)        { og = 4 + ((c - 36) >> 3); j = (c - 36) & 7; }
        if (og >= 0 && j < 5) v = Win[(og * 5 + j) * NIN + k];
        Wt_g[i] = v;
    }
    if (i < NL * 16 * DD * 12) {
        int e = i % 12;
        int r = i / 12;
        float v = 0.0f;
        if (e < DD) v = dw[r * DD + e];
        dwp_g[i] = v;
    }
}

__device__ __forceinline__ void ffma2(ull &d, ull a, ull b) {
    asm("fma.rn.f32x2 %0, %1, %2, %0;" : "+l"(d) : "l"(a), "l"(b));
}
__device__ __forceinline__ ull pack2(float lo, float hi) {
    ull r; asm("mov.b64 %0, {%1, %2};" : "=l"(r) : "f"(lo), "f"(hi)); return r;
}
__device__ __forceinline__ void unpack2(ull v, float &lo, float &hi) {
    asm("mov.b64 {%0, %1}, %2;" : "=f"(lo), "=f"(hi) : "l"(v));
}

__global__ void __launch_bounds__(TPB, 2)
routenet_kernel(const float* __restrict__ x,
                const float* __restrict__ bin,
                const float* __restrict__ gw,
                const float* __restrict__ db,
                const float* __restrict__ wout,
                float* __restrict__ out,
                int B)
{
    __shared__ __align__(16) float WcS[2][16 * WROW];     // 2 x 4352 B
    __shared__ __align__(16) float gws[NL * 16 * DD];
    __shared__ __align__(16) float dbs[NL * 16 * DD];
    __shared__ __align__(16) float wouts[WW * NOUT * DD];
    __shared__ __align__(16) float bins[40];
    __shared__ __align__(16) float acts[ROWS_PB * 41];    // 10496 B

    const int tid  = threadIdx.x;
    const int warp = tid >> 5;
    const int lane = tid & 31;
    const int og   = lane & 7;        // outputs og*5 .. og*5+4
    const int ks   = lane >> 3;       // k strip 0..3
    const int wcol = og * 8 + (og & 4);

    for (int i = tid; i < NL * 16 * DD; i += TPB) { gws[i] = gw[i]; dbs[i] = db[i]; }
    for (int i = tid; i < WW * NOUT * DD; i += TPB) wouts[i] = wout[i];
    if (tid < 40) bins[tid] = bin[tid];

    const int row0 = blockIdx.x * ROWS_PB + warp * 8;
    const float* xr = x + (size_t)row0 * NIN;

    // prologue: stage W chunk 0
    {
        const float* src = Wt_g;
        for (int i = tid; i < STG16; i += TPB)
            __pipeline_memcpy_async(&WcS[0][i * 4], src + i * 4, 16);
        __pipeline_commit();
    }

    ull acc[4][5];
    #pragma unroll
    for (int p = 0; p < 4; ++p)
        #pragma unroll
        for (int j = 0; j < 5; ++j) acc[p][j] = 0ull;

    // =====================================================================
    // Phase 1: warp-shared 8 rows; lane = (ks, og); x LDG = 1 line/instr
    // =====================================================================
    #pragma unroll 1
    for (int c = 0; c < NC; ++c) {
        __syncthreads();                       // buf[(c+1)&1] readers done
        if (c + 1 < NC) {
            const float* src = Wt_g + (size_t)(c + 1) * (16 * WROW);
            float* dst = WcS[(c + 1) & 1];
            for (int i = tid; i < STG16; i += TPB)
                __pipeline_memcpy_async(&dst[i * 4], src + i * 4, 16);
            __pipeline_commit();
        }

        // x: 8 rows x 4 k (this thread's strip); 1 line per LDG.128
        float4 xs[8];
        #pragma unroll
        for (int r = 0; r < 8; ++r)
            xs[r] = __ldg((const float4*)(xr + r * NIN + c * 16 + ks * 4));

        if (c + 1 < NC) __pipeline_wait_prior(1);
        else            __pipeline_wait_prior(0);
        __syncthreads();                       // stage c visible to all

        const float* Wb = WcS[c & 1];
        #pragma unroll
        for (int kk = 0; kk < 4; ++kk) {
            const float* wrow = Wb + (ks * 4 + kk) * WROW + wcol;
            float4 wa = *(const float4*)wrow;  // LDS.128, swizzle-conflict-free
            float  w4 = wrow[4];               // LDS.32
            float wv[5] = {wa.x, wa.y, wa.z, wa.w, w4};

            ull xp[4];
            #pragma unroll
            for (int p = 0; p < 4; ++p) {
                float xlo = (kk == 0) ? xs[2*p].x : (kk == 1) ? xs[2*p].y
                          : (kk == 2) ? xs[2*p].z : xs[2*p].w;
                float xhi = (kk == 0) ? xs[2*p+1].x : (kk == 1) ? xs[2*p+1].y
                          : (kk == 2) ? xs[2*p+1].z : xs[2*p+1].w;
                xp[p] = pack2(xlo, xhi);
            }
            #pragma unroll
            for (int j = 0; j < 5; ++j) {
                ull wd = pack2(wv[j], wv[j]);
                ffma2(acc[0][j], xp[0], wd);
                ffma2(acc[1][j], xp[1], wd);
                ffma2(acc[2][j], xp[2], wd);
                ffma2(acc[3][j], xp[3], wd);
            }
        }
    }

    // reduce across ks strips (lanes differing in bits 3,4)
    #pragma unroll
    for (int p = 0; p < 4; ++p)
        #pragma unroll
        for (int j = 0; j < 5; ++j) {
            ull v = acc[p][j];
            float lo, hi, olo, ohi;
            unpack2(v, lo, hi);
            olo = __shfl_xor_sync(0xffffffffu, lo, 8);
            ohi = __shfl_xor_sync(0xffffffffu, hi, 8);
            lo += olo; hi += ohi;
            olo = __shfl_xor_sync(0xffffffffu, lo, 16);
            ohi = __shfl_xor_sync(0xffffffffu, hi, 16);
            lo += olo; hi += ohi;
            acc[p][j] = pack2(lo, hi);
        }

    // ks==0 lanes write acts (bias + relu)
    if (ks == 0) {
        #pragma unroll
        for (int p = 0; p < 4; ++p)
            #pragma unroll
            for (int j = 0; j < 5; ++j) {
                int o = og * 5 + j;
                float b = bins[o];
                float lo, hi; unpack2(acc[p][j], lo, hi);
                acts[(warp * 8 + 2 * p)     * 41 + o] = fmaxf(lo + b, 0.0f);
                acts[(warp * 8 + 2 * p + 1) * 41 + o] = fmaxf(hi + b, 0.0f);
            }
    }
    __syncthreads();

    // =====================================================================
    // Phases 2-4: threads 0..63, one row each; weights warp-uniform LDG
    // =====================================================================
    if (tid < ROWS_PB) {
        float a[WW][DD];
        #pragma unroll
        for (int w = 0; w < WW; ++w)
            #pragma unroll
            for (int d = 0; d < DD; ++d)
                a[w][d] = acts[tid * 41 + w * DD + d];

        float tg = 0.0f;

        #pragma unroll 1
        for (int l = 0; l < NL; ++l) {
            const float* gwl = gws + l * 160;
            const float* dbl = dbs + l * 160;
            const float* dwl = dwp_g + l * 16 * 120;

            ull nxt[WW][5];
            #pragma unroll
            for (int t = 0; t < WW; ++t)
                #pragma unroll
                for (int j = 0; j < 5; ++j) nxt[t][j] = 0ull;

            #pragma unroll
            for (int s = 0; s < WW; ++s) {
                ull a2[DD];
                #pragma unroll
                for (int d = 0; d < DD; ++d) a2[d] = pack2(a[s][d], a[s][d]);

                #pragma unroll
                for (int t = 0; t < WW; ++t) {
                    const int edge = s * WW + t;

                    const float* gv = gwl + edge * DD;
                    float g = 0.0f;
                    #pragma unroll
                    for (int d = 0; d < DD; ++d) g += a[s][d] * gv[d];
                    g = fminf(fmaxf(g, 0.0f), 1.0f);
                    tg += g;
                    ull g2 = pack2(g, g);

                    ull m[5];
                    const ull* bv = (const ull*)(dbl + edge * DD);
                    #pragma unroll
                    for (int j = 0; j < 5; ++j) m[j] = bv[j];

                    const float* drow = dwl + edge * 120;
                    #pragma unroll
                    for (int din = 0; din < DD; ++din) {
                        const char* rp = (const char*)(drow + din * 12);
                        ulonglong2 wA = __ldg((const ulonglong2*)rp);
                        ulonglong2 wB = __ldg((const ulonglong2*)(rp + 16));
                        ull        wC = __ldg((const ull*)(rp + 32));
                        ull ad = a2[din];
                        ffma2(m[0], ad, wA.x);
                        ffma2(m[1], ad, wA.y);
                        ffma2(m[2], ad, wB.x);
                        ffma2(m[3], ad, wB.y);
                        ffma2(m[4], ad, wC);
                    }

                    #pragma unroll
                    for (int j = 0; j < 5; ++j) ffma2(nxt[t][j], g2, m[j]);
                }
            }

            #pragma unroll
            for (int t = 0; t < WW; ++t)
                #pragma unroll
                for (int j = 0; j < 5; ++j) {
                    float lo, hi; unpack2(nxt[t][j], lo, hi);
                    a[t][2 * j]     = fmaxf(lo, 0.0f);
                    a[t][2 * j + 1] = fmaxf(hi, 0.0f);
                }
        }

        // output banks + total_gate
        const size_t row = (size_t)blockIdx.x * ROWS_PB + tid;
        float ov[NOUT];
        #pragma unroll
        for (int c2 = 0; c2 < NOUT; ++c2) {
            float o = 0.0f;
            #pragma unroll
            for (int w = 0; w < WW; ++w)
                #pragma unroll
                for (int d = 0; d < DD; ++d)
                    o += a[w][d] * wouts[(w * NOUT + c2) * DD + d];
            ov[c2] = o;
        }
        float2* op = (float2*)(out + row * NOUT);
        #pragma unroll
        for (int j = 0; j < 5; ++j) op[j] = make_float2(ov[2 * j], ov[2 * j + 1]);
        out[(size_t)B * NOUT + row] = tg;
    }
}

extern "C" void kernel_launch(void* const* d_in, const int* in_sizes, int n_in,
                              void* d_out, int out_size)
{
    const float* x    = (const float*)d_in[0];
    const float* Win  = (const float*)d_in[1];
    const float* bin  = (const float*)d_in[2];
    const float* gw   = (const float*)d_in[3];
    const float* dw   = (const float*)d_in[4];
    const float* db   = (const float*)d_in[5];
    const float* wout = (const float*)d_in[6];

    const int B = in_sizes[0] / NIN;

    prep_kernel<<<(NIN * WROW + TPB - 1) / TPB, TPB>>>(Win, dw);
    routenet_kernel<<<B / ROWS_PB, TPB>>>(x, bin, gw, db, wout,
                                          (float*)d_out, B);
}

// round 8
// speedup vs baseline: 1.4580x; 1.4580x over previous
#include <cuda_runtime.h>

typedef unsigned long long ull;

#define NIN   784
#define DD    10
#define WW    4
#define NOUT  10
#define NL    3
#define NC    49            // 784/16 k-chunks
#define BMAX  131072

// __device__ scratch (no allocation)
__device__ float Wt3_g[NC * 5 * 32 * 4];      // lane-interleaved Win, 5 float4 planes/chunk
__device__ float dwp_g[NL * 16 * DD * 12];    // data_w, e padded 10->12
__device__ float acts0_g[(size_t)BMAX * 40];  // phase-1 output

__global__ void prep_kernel(const float* __restrict__ Win,
                            const float* __restrict__ dw)
{
    int i = blockIdx.x * blockDim.x + threadIdx.x;
    if (i < NC * 5 * 32 * 4) {
        int q    = i & 3;
        int lane = (i >> 2) & 31;
        int t2   = i >> 7;
        int ip   = t2 % 5;
        int c    = t2 / 5;
        int idx  = ip * 4 + q;        // 0..19
        int kk   = idx / 5;
        int j    = idx % 5;
        int og   = lane & 7;
        int ks   = lane >> 3;
        int k    = c * 16 + ks * 4 + kk;
        Wt3_g[i] = Win[(og * 5 + j) * NIN + k];
    }
    if (i < NL * 16 * DD * 12) {
        int e = i % 12;
        int r = i / 12;
        dwp_g[i] = (e < DD) ? dw[r * DD + e] : 0.0f;
    }
}

__device__ __forceinline__ void ffma2(ull &d, ull a, ull b) {
    asm("fma.rn.f32x2 %0, %1, %2, %0;" : "+l"(d) : "l"(a), "l"(b));
}
__device__ __forceinline__ ull pack2(float lo, float hi) {
    ull r; asm("mov.b64 %0, {%1, %2};" : "=l"(r) : "f"(lo), "f"(hi)); return r;
}
__device__ __forceinline__ void unpack2(ull v, float &lo, float &hi) {
    asm("mov.b64 {%0, %1}, %2;" : "=f"(lo), "=f"(hi) : "l"(v));
}

// ============================================================================
// Kernel A: acts0 = relu(x @ Win^T + b_in).  Warp = 8 rows; lane = (ks, og).
// No block barriers; x LDG = 1 line/instr; W LDG fully coalesced.
// ============================================================================
__global__ void __launch_bounds__(256, 2)
phase1_kernel(const float* __restrict__ x,
              const float* __restrict__ bin,
              int B)
{
    const int tid  = threadIdx.x;
    const int warp = tid >> 5;
    const int lane = tid & 31;
    const int og   = lane & 7;
    const int ks   = lane >> 3;

    const int row0 = blockIdx.x * 64 + warp * 8;
    const float* xr = x + (size_t)row0 * NIN;

    ull acc[4][5];
    #pragma unroll
    for (int p = 0; p < 4; ++p)
        #pragma unroll
        for (int j = 0; j < 5; ++j) acc[p][j] = 0ull;

    #pragma unroll 1
    for (int c = 0; c < NC; ++c) {
        // W: 5 coalesced LDG.128 (20 floats for this lane's (ks,og) slice)
        float4 wq[5];
        const float4* wp = (const float4*)Wt3_g + (size_t)(c * 5) * 32 + lane;
        #pragma unroll
        for (int i = 0; i < 5; ++i) wq[i] = __ldg(wp + i * 32);
        float w[20];
        #pragma unroll
        for (int i = 0; i < 5; ++i) {
            w[i * 4 + 0] = wq[i].x; w[i * 4 + 1] = wq[i].y;
            w[i * 4 + 2] = wq[i].z; w[i * 4 + 3] = wq[i].w;
        }

        // x: 8 rows x this lane's 4-k strip; each LDG.128 touches 1 line
        float4 xs[8];
        #pragma unroll
        for (int r = 0; r < 8; ++r)
            xs[r] = __ldg((const float4*)(xr + r * NIN + c * 16 + ks * 4));

        #pragma unroll
        for (int kk = 0; kk < 4; ++kk) {
            ull xp[4];
            #pragma unroll
            for (int p = 0; p < 4; ++p) {
                float xlo = (kk == 0) ? xs[2*p].x : (kk == 1) ? xs[2*p].y
                          : (kk == 2) ? xs[2*p].z : xs[2*p].w;
                float xhi = (kk == 0) ? xs[2*p+1].x : (kk == 1) ? xs[2*p+1].y
                          : (kk == 2) ? xs[2*p+1].z : xs[2*p+1].w;
                xp[p] = pack2(xlo, xhi);
            }
            #pragma unroll
            for (int j = 0; j < 5; ++j) {
                float wv = w[kk * 5 + j];
                ull wd = pack2(wv, wv);
                ffma2(acc[0][j], xp[0], wd);
                ffma2(acc[1][j], xp[1], wd);
                ffma2(acc[2][j], xp[2], wd);
                ffma2(acc[3][j], xp[3], wd);
            }
        }
    }

    // reduce across ks strips (full sums land in every lane)
    #pragma unroll
    for (int p = 0; p < 4; ++p)
        #pragma unroll
        for (int j = 0; j < 5; ++j) {
            float lo, hi, olo, ohi;
            unpack2(acc[p][j], lo, hi);
            olo = __shfl_xor_sync(0xffffffffu, lo, 8);
            ohi = __shfl_xor_sync(0xffffffffu, hi, 8);
            lo += olo; hi += ohi;
            olo = __shfl_xor_sync(0xffffffffu, lo, 16);
            ohi = __shfl_xor_sync(0xffffffffu, hi, 16);
            lo += olo; hi += ohi;
            acc[p][j] = pack2(lo, hi);
        }

    // bias + relu + store: lane handles rows (2ks, 2ks+1), cols og*5..og*5+4
    #pragma unroll
    for (int p = 0; p < 4; ++p) {
        if (ks == p) {
            #pragma unroll
            for (int j = 0; j < 5; ++j) {
                int o = og * 5 + j;
                float b = __ldg(bin + o);
                float lo, hi; unpack2(acc[p][j], lo, hi);
                acts0_g[(size_t)(row0 + 2 * p)     * 40 + o] = fmaxf(lo + b, 0.0f);
                acts0_g[(size_t)(row0 + 2 * p + 1) * 40 + o] = fmaxf(hi + b, 0.0f);
            }
        }
    }
}

// ============================================================================
// Kernel B: routed layers 2-4 + output banks.  1 row/thread, weights via
// warp-uniform LDG (1 line/instr) -- proven R6 structure.
// ============================================================================
__global__ void __launch_bounds__(256, 2)
phase2_kernel(const float* __restrict__ gw,
              const float* __restrict__ db,
              const float* __restrict__ wout,
              float* __restrict__ out,
              int B)
{
    __shared__ __align__(16) float gws[NL * 16 * DD];
    __shared__ __align__(16) float dbs[NL * 16 * DD];
    __shared__ __align__(16) float wouts[WW * NOUT * DD];

    const int tid = threadIdx.x;
    for (int i = tid; i < NL * 16 * DD; i += 256) { gws[i] = gw[i]; dbs[i] = db[i]; }
    for (int i = tid; i < WW * NOUT * DD; i += 256) wouts[i] = wout[i];
    __syncthreads();

    const size_t row = (size_t)blockIdx.x * 256 + tid;

    float a[WW][DD];
    {
        const float4* ap = (const float4*)(acts0_g + row * 40);
        #pragma unroll
        for (int i = 0; i < 10; ++i) {
            float4 v = __ldg(ap + i);
            int o = i * 4;
            a[o / DD][o % DD]           = v.x;
            a[(o+1) / DD][(o+1) % DD]   = v.y;
            a[(o+2) / DD][(o+2) % DD]   = v.z;
            a[(o+3) / DD][(o+3) % DD]   = v.w;
        }
    }

    float tg = 0.0f;

    #pragma unroll 1
    for (int l = 0; l < NL; ++l) {
        const float* gwl = gws + l * 160;
        const float* dbl = dbs + l * 160;
        const float* dwl = dwp_g + l * 16 * 120;

        ull nxt[WW][5];
        #pragma unroll
        for (int t = 0; t < WW; ++t)
            #pragma unroll
            for (int j = 0; j < 5; ++j) nxt[t][j] = 0ull;

        #pragma unroll
        for (int s = 0; s < WW; ++s) {
            ull a2[DD];
            #pragma unroll
            for (int d = 0; d < DD; ++d) a2[d] = pack2(a[s][d], a[s][d]);

            #pragma unroll
            for (int t = 0; t < WW; ++t) {
                const int edge = s * WW + t;

                const float* gv = gwl + edge * DD;
                float g = 0.0f;
                #pragma unroll
                for (int d = 0; d < DD; ++d) g += a[s][d] * gv[d];
                g = fminf(fmaxf(g, 0.0f), 1.0f);
                tg += g;
                ull g2 = pack2(g, g);

                ull m[5];
                const ull* bv = (const ull*)(dbl + edge * DD);
                #pragma unroll
                for (int j = 0; j < 5; ++j) m[j] = bv[j];

                const float* drow = dwl + edge * 120;
                #pragma unroll
                for (int din = 0; din < DD; ++din) {
                    const char* rp = (const char*)(drow + din * 12);
                    ulonglong2 wA = __ldg((const ulonglong2*)rp);
                    ulonglong2 wB = __ldg((const ulonglong2*)(rp + 16));
                    ull        wC = __ldg((const ull*)(rp + 32));
                    ull ad = a2[din];
                    ffma2(m[0], ad, wA.x);
                    ffma2(m[1], ad, wA.y);
                    ffma2(m[2], ad, wB.x);
                    ffma2(m[3], ad, wB.y);
                    ffma2(m[4], ad, wC);
                }

                #pragma unroll
                for (int j = 0; j < 5; ++j) ffma2(nxt[t][j], g2, m[j]);
            }
        }

        #pragma unroll
        for (int t = 0; t < WW; ++t)
            #pragma unroll
            for (int j = 0; j < 5; ++j) {
                float lo, hi; unpack2(nxt[t][j], lo, hi);
                a[t][2 * j]     = fmaxf(lo, 0.0f);
                a[t][2 * j + 1] = fmaxf(hi, 0.0f);
            }
    }

    float ov[NOUT];
    #pragma unroll
    for (int c = 0; c < NOUT; ++c) {
        float o = 0.0f;
        #pragma unroll
        for (int w = 0; w < WW; ++w)
            #pragma unroll
            for (int d = 0; d < DD; ++d)
                o += a[w][d] * wouts[(w * NOUT + c) * DD + d];
        ov[c] = o;
    }
    float2* op = (float2*)(out + row * NOUT);
    #pragma unroll
    for (int j = 0; j < 5; ++j) op[j] = make_float2(ov[2 * j], ov[2 * j + 1]);
    out[(size_t)B * NOUT + row] = tg;
}

extern "C" void kernel_launch(void* const* d_in, const int* in_sizes, int n_in,
                              void* d_out, int out_size)
{
    const float* x    = (const float*)d_in[0];
    const float* Win  = (const float*)d_in[1];
    const float* bin  = (const float*)d_in[2];
    const float* gw   = (const float*)d_in[3];
    const float* dw   = (const float*)d_in[4];
    const float* db   = (const float*)d_in[5];
    const float* wout = (const float*)d_in[6];

    const int B = in_sizes[0] / NIN;

    prep_kernel<<<(NC * 5 * 32 * 4 + 255) / 256, 256>>>(Win, dw);
    phase1_kernel<<<B / 64, 256>>>(x, bin, B);
    phase2_kernel<<<B / 256, 256>>>(gw, db, wout, (float*)d_out, B);
}